// round 2
// baseline (speedup 1.0000x reference)
#include <cuda_runtime.h>

// DeepseekV3TopkRouter: scores = sigmoid(X @ W^T + b); grouped top-k routing.
// Kernel 1: fp32 GEMM (packed f32x2 FFMA, two-level Kahan-compensated
//           accumulation for near-exact logits) + sigmoid -> g_scores
// Kernel 2: warp-per-token grouped top-k + weight normalization
//
// Output layout (flattened tuple concat, float32):
//   d_out[0 .. T*8)          = topk_indices (as float)
//   d_out[T*8 .. 2*T*8)      = topk_weights

#define HDIM 7168
#define NEXP 256
#define TOPK 8
#define NGRP 8
#define TKG  4
#define SCALE_F 2.5f

#define BM 128
#define BN 128
#define BK 16
#define NTHR 256
#define FOLD_SLABS 2   // Kahan-fold acc_lo -> acc_hi every 2 slabs (32 k-terms)

#define MAX_T 8192

__device__ float g_scores[MAX_T * NEXP];

typedef unsigned long long ull;

__device__ __forceinline__ ull dup_f32(float x) {
    ull r;
    asm("mov.b64 %0, {%1, %1};" : "=l"(r) : "f"(x));
    return r;
}
// acc = a*b + acc (packed)
__device__ __forceinline__ void fma2_acc(ull& acc, ull a, ull b) {
    asm("fma.rn.f32x2 %0, %1, %2, %0;" : "+l"(acc) : "l"(a), "l"(b));
}
// d = a*b + c (packed)
__device__ __forceinline__ ull fma2(ull a, ull b, ull c) {
    ull d;
    asm("fma.rn.f32x2 %0, %1, %2, %3;" : "=l"(d) : "l"(a), "l"(b), "l"(c));
    return d;
}
// d = a + b (packed)
__device__ __forceinline__ ull add2(ull a, ull b) {
    ull d;
    asm("add.rn.f32x2 %0, %1, %2;" : "=l"(d) : "l"(a), "l"(b));
    return d;
}
__device__ __forceinline__ float2 unpack_f32x2(ull v) {
    float lo, hi;
    asm("mov.b64 {%0, %1}, %2;" : "=f"(lo), "=f"(hi) : "l"(v));
    return make_float2(lo, hi);
}

__global__ __launch_bounds__(NTHR, 1)
void gemm_sigmoid_kernel(const float* __restrict__ A,    // [T, HDIM]
                         const float* __restrict__ W,    // [NEXP, HDIM]
                         const float* __restrict__ bvec, // [NEXP]
                         int T)
{
    __shared__ __align__(16) float As[2][BK][BM + 4];
    __shared__ __align__(16) float Bs[2][BK][BN + 4];

    const int tid = threadIdx.x;
    const int bm = blockIdx.y * BM;
    const int bn = blockIdx.x * BN;

    const int tr8 = (tid >> 4) * 8;   // 0..120
    const int tc8 = (tid & 15) * 8;   // 0..120

    // Global load mapping: 2 float4 of A and W per thread per BK-slab.
    const int a_row0 = (tid + 0)   >> 2, a_c40 = (tid + 0)   & 3;
    const int a_row1 = (tid + 256) >> 2, a_c41 = (tid + 256) & 3;

    const float* Aptr0 = A + (size_t)(bm + a_row0) * HDIM + a_c40 * 4;
    const float* Aptr1 = A + (size_t)(bm + a_row1) * HDIM + a_c41 * 4;
    const float* Wptr0 = W + (size_t)(bn + a_row0) * HDIM + a_c40 * 4;
    const float* Wptr1 = W + (size_t)(bn + a_row1) * HDIM + a_c41 * 4;

    const ull neg1 = dup_f32(-1.0f);

    ull acc_lo[8][4], acc_hi[8][4], comp[8][4];
#pragma unroll
    for (int i = 0; i < 8; ++i)
#pragma unroll
        for (int j = 0; j < 4; ++j) {
            acc_lo[i][j] = 0ull; acc_hi[i][j] = 0ull; comp[i][j] = 0ull;
        }

    float4 aR0, aR1, bR0, bR1;

    // prologue: load slab 0
    aR0 = *(const float4*)(Aptr0);
    aR1 = *(const float4*)(Aptr1);
    bR0 = *(const float4*)(Wptr0);
    bR1 = *(const float4*)(Wptr1);
    {
        As[0][a_c40 * 4 + 0][a_row0] = aR0.x;
        As[0][a_c40 * 4 + 1][a_row0] = aR0.y;
        As[0][a_c40 * 4 + 2][a_row0] = aR0.z;
        As[0][a_c40 * 4 + 3][a_row0] = aR0.w;
        As[0][a_c41 * 4 + 0][a_row1] = aR1.x;
        As[0][a_c41 * 4 + 1][a_row1] = aR1.y;
        As[0][a_c41 * 4 + 2][a_row1] = aR1.z;
        As[0][a_c41 * 4 + 3][a_row1] = aR1.w;
        Bs[0][a_c40 * 4 + 0][a_row0] = bR0.x;
        Bs[0][a_c40 * 4 + 1][a_row0] = bR0.y;
        Bs[0][a_c40 * 4 + 2][a_row0] = bR0.z;
        Bs[0][a_c40 * 4 + 3][a_row0] = bR0.w;
        Bs[0][a_c41 * 4 + 0][a_row1] = bR1.x;
        Bs[0][a_c41 * 4 + 1][a_row1] = bR1.y;
        Bs[0][a_c41 * 4 + 2][a_row1] = bR1.z;
        Bs[0][a_c41 * 4 + 3][a_row1] = bR1.w;
    }
    __syncthreads();

    const int NIT = HDIM / BK;   // 448
    int buf = 0;

    for (int it = 0; it < NIT; ++it) {
        const bool has_next = (it + 1) < NIT;
        if (has_next) {
            const int koff = (it + 1) * BK;
            aR0 = *(const float4*)(Aptr0 + koff);
            aR1 = *(const float4*)(Aptr1 + koff);
            bR0 = *(const float4*)(Wptr0 + koff);
            bR1 = *(const float4*)(Wptr1 + koff);
        }

#pragma unroll
        for (int k = 0; k < BK; ++k) {
            const float* arow = &As[buf][k][tr8];
            float4 a0 = *(const float4*)(arow);
            float4 a1 = *(const float4*)(arow + 4);
            const ulonglong2 b01 = *(const ulonglong2*)(&Bs[buf][k][tc8]);
            const ulonglong2 b23 = *(const ulonglong2*)(&Bs[buf][k][tc8 + 4]);
            ull bp[4];
            bp[0] = b01.x; bp[1] = b01.y; bp[2] = b23.x; bp[3] = b23.y;
            ull ap[8];
            ap[0] = dup_f32(a0.x); ap[1] = dup_f32(a0.y);
            ap[2] = dup_f32(a0.z); ap[3] = dup_f32(a0.w);
            ap[4] = dup_f32(a1.x); ap[5] = dup_f32(a1.y);
            ap[6] = dup_f32(a1.z); ap[7] = dup_f32(a1.w);
#pragma unroll
            for (int i = 0; i < 8; ++i)
#pragma unroll
                for (int j = 0; j < 4; ++j)
                    fma2_acc(acc_lo[i][j], ap[i], bp[j]);
        }

        // Kahan-compensated fold of acc_lo into acc_hi every FOLD_SLABS slabs.
        if ((it % FOLD_SLABS) == (FOLD_SLABS - 1)) {
#pragma unroll
            for (int i = 0; i < 8; ++i)
#pragma unroll
                for (int j = 0; j < 4; ++j) {
                    ull y = fma2(comp[i][j], neg1, acc_lo[i][j]);   // lo - comp
                    ull t = add2(acc_hi[i][j], y);                  // hi + y
                    ull d = fma2(acc_hi[i][j], neg1, t);            // t - hi
                    comp[i][j] = fma2(y, neg1, d);                  // (t-hi) - y
                    acc_hi[i][j] = t;
                    acc_lo[i][j] = 0ull;
                }
        }

        if (has_next) {
            const int nb = buf ^ 1;
            As[nb][a_c40 * 4 + 0][a_row0] = aR0.x;
            As[nb][a_c40 * 4 + 1][a_row0] = aR0.y;
            As[nb][a_c40 * 4 + 2][a_row0] = aR0.z;
            As[nb][a_c40 * 4 + 3][a_row0] = aR0.w;
            As[nb][a_c41 * 4 + 0][a_row1] = aR1.x;
            As[nb][a_c41 * 4 + 1][a_row1] = aR1.y;
            As[nb][a_c41 * 4 + 2][a_row1] = aR1.z;
            As[nb][a_c41 * 4 + 3][a_row1] = aR1.w;
            Bs[nb][a_c40 * 4 + 0][a_row0] = bR0.x;
            Bs[nb][a_c40 * 4 + 1][a_row0] = bR0.y;
            Bs[nb][a_c40 * 4 + 2][a_row0] = bR0.z;
            Bs[nb][a_c40 * 4 + 3][a_row0] = bR0.w;
            Bs[nb][a_c41 * 4 + 0][a_row1] = bR1.x;
            Bs[nb][a_c41 * 4 + 1][a_row1] = bR1.y;
            Bs[nb][a_c41 * 4 + 2][a_row1] = bR1.z;
            Bs[nb][a_c41 * 4 + 3][a_row1] = bR1.w;
            __syncthreads();
            buf = nb;
        }
    }

    // epilogue: Neumaier correction, add bias, sigmoid, store scores
#pragma unroll
    for (int i = 0; i < 8; ++i) {
        const int m = bm + tr8 + i;
        float* orow = &g_scores[(size_t)m * NEXP + bn + tc8];
#pragma unroll
        for (int jp = 0; jp < 4; ++jp) {
            ull r = fma2(comp[i][jp], neg1, acc_hi[i][jp]);  // hi - comp
            float2 v = unpack_f32x2(r);
            const int n = bn + tc8 + jp * 2;
            float l0 = v.x + bvec[n];
            float l1 = v.y + bvec[n + 1];
            orow[0] = 1.0f / (1.0f + expf(-l0));
            orow[1] = 1.0f / (1.0f + expf(-l1));
            orow += 2;
        }
    }
}

// ---------------- routing kernel: one warp per token ----------------

__global__ __launch_bounds__(128)
void router_kernel(const float* __restrict__ ebias,  // [NEXP]
                   float* __restrict__ out,          // [2*T*TOPK] (idx then w)
                   int T)
{
    __shared__ float raw_s[4][NEXP];
    const int warp = threadIdx.x >> 5;
    const int lane = threadIdx.x & 31;
    const int t = blockIdx.x * 4 + warp;
    if (t >= T) return;

    const float NEG_INF = __int_as_float(0xff800000);

    float* rs = raw_s[warp];
    float sfc[8];    // expert e = i*32 + lane (group i spread across lanes)
#pragma unroll
    for (int i = 0; i < 8; ++i) {
        const int e = i * 32 + lane;
        const float s = g_scores[(size_t)t * NEXP + e];
        rs[e] = s;
        sfc[i] = s + ebias[e];
    }
    __syncwarp();

    // per-group top-2 sum (warp reduce over the 32 lanes of each group)
    float gs[8];
#pragma unroll
    for (int i = 0; i < 8; ++i) {
        float m1 = sfc[i], m2 = NEG_INF;
#pragma unroll
        for (int off = 16; off > 0; off >>= 1) {
            float o1 = __shfl_xor_sync(0xffffffffu, m1, off);
            float o2 = __shfl_xor_sync(0xffffffffu, m2, off);
            float hi = fmaxf(m1, o1);
            float lo = fminf(m1, o1);
            m1 = hi;
            m2 = fmaxf(fmaxf(m2, o2), lo);
        }
        gs[i] = m1 + m2;
    }

    // top-4 groups (strict > keeps lowest index on ties, matching jax top_k)
    unsigned gmask = 0;
#pragma unroll
    for (int j = 0; j < TKG; ++j) {
        float best = NEG_INF;
        int bg = 0;
#pragma unroll
        for (int g = 0; g < NGRP; ++g) {
            if (!((gmask >> g) & 1u) && gs[g] > best) { best = gs[g]; bg = g; }
        }
        gmask |= (1u << bg);
    }

    // masked candidate values: unselected groups -> 0.0 (as in reference)
    float cv[8];
#pragma unroll
    for (int i = 0; i < 8; ++i)
        cv[i] = ((gmask >> i) & 1u) ? sfc[i] : 0.0f;

    // top-8 experts, descending, lowest index on ties
    unsigned used = 0;
    int idxs[8];
#pragma unroll
    for (int j = 0; j < TOPK; ++j) {
        float bv = NEG_INF;
        int be = 1 << 30;
#pragma unroll
        for (int i = 0; i < 8; ++i) {
            if (!((used >> i) & 1u)) {
                const float v = cv[i];
                const int e = i * 32 + lane;
                if (v > bv || (v == bv && e < be)) { bv = v; be = e; }
            }
        }
#pragma unroll
        for (int off = 16; off > 0; off >>= 1) {
            float ov = __shfl_xor_sync(0xffffffffu, bv, off);
            int oe = __shfl_xor_sync(0xffffffffu, be, off);
            if (ov > bv || (ov == bv && oe < be)) { bv = ov; be = oe; }
        }
        idxs[j] = be;
        if ((be & 31) == lane) used |= (1u << (be >> 5));
    }

    // weights from raw sigmoid scores; normalize; scale
    float wj = 0.0f;
    if (lane < TOPK) wj = rs[idxs[lane]];
    float ssum = wj;
#pragma unroll
    for (int off = 4; off > 0; off >>= 1)
        ssum += __shfl_xor_sync(0xffffffffu, ssum, off);
    const float denom = ssum + 1e-20f;

    if (lane < TOPK) {
        out[(size_t)t * TOPK + lane] = (float)idxs[lane];
        out[(size_t)T * TOPK + (size_t)t * TOPK + lane] = wj / denom * SCALE_F;
    }
}

extern "C" void kernel_launch(void* const* d_in, const int* in_sizes, int n_in,
                              void* d_out, int out_size)
{
    const float* hs = (const float*)d_in[0];   // [T, HDIM]
    const float* W  = (const float*)d_in[1];   // [NEXP, HDIM]
    const float* b  = (const float*)d_in[2];   // [NEXP]
    const float* eb = (const float*)d_in[3];   // [NEXP]
    const int T = in_sizes[0] / HDIM;

    dim3 grid(NEXP / BN, T / BM);
    gemm_sigmoid_kernel<<<grid, NTHR>>>(hs, W, b, T);

    const int nb = (T + 3) / 4;
    router_kernel<<<nb, 128>>>(eb, (float*)d_out, T);
}